// round 2
// baseline (speedup 1.0000x reference)
#include <cuda_runtime.h>
#include <cstdint>
#include <cstddef>

// ---------------------------------------------------------------------------
// Persistent grouped-RNN kernel.
//   B=512 batch rows split into 16 independent groups of 32 rows.
//   Each group: 8 CTAs, each owning 64 of the 512 output columns.
//   Sync: per-group 8-CTA atomic barrier (all 128 CTAs co-resident).
//   GEMM: mma.sync m16n8k8 tf32, K extended to 528 to fold in x @ W_ih.
//   W slice + fused W_ih slice live in smem (tf32) for the whole kernel.
// ---------------------------------------------------------------------------

namespace {
constexpr int Bb = 512;
constexpr int Hh = 512;
constexpr int Ii = 13;
constexpr int GROUPS = 16;
constexpr int CPG = 8;          // CTAs per group
constexpr int MT = 32;          // rows per group / CTA tile M
constexpr int NT = 64;          // cols per CTA
constexpr int THREADS = 256;    // 8 warps: 2 (M) x 4 (N), warp tile 16x16
constexpr int KK = 528;         // 512 + 13 input cols + 3 zero pad
constexpr int STR = 532;        // smem row stride (floats); %8==4 -> conflict-free frag loads
constexpr int WS_OFF = 0;                    // Ws: [NT][STR]
constexpr int AS_OFF = NT * STR;             // As: [MT][STR]
constexpr int BIAS_OFF = AS_OFF + MT * STR;  // bias: [NT]
constexpr int SMEM_FLOATS = BIAS_OFF + NT;
constexpr int SMEM_BYTES = SMEM_FLOATS * 4;  // 204,544 B
constexpr float LEAK = 0.8f;
constexpr float ALPHA_ = 0.2f;
constexpr float SIGMA_ = 0.15811388300841898f;  // sqrt(2/0.2) * 0.05
}

__device__ unsigned g_bar[GROUPS];

__device__ __forceinline__ unsigned ld_acq(const unsigned* p) {
    unsigned v;
    asm volatile("ld.acquire.gpu.u32 %0, [%1];" : "=r"(v) : "l"(p));
    return v;
}

__device__ __forceinline__ uint32_t tf32_rna(float x) {
    uint32_t r;
    asm("cvt.rna.tf32.f32 %0, %1;" : "=r"(r) : "f"(x));
    return r;
}
__device__ __forceinline__ float tf32f(float x) { return __uint_as_float(tf32_rna(x)); }

__device__ __forceinline__ void mma_tf32(float c[4], uint32_t a0, uint32_t a1,
                                         uint32_t a2, uint32_t a3,
                                         uint32_t b0, uint32_t b1) {
    asm volatile(
        "mma.sync.aligned.m16n8k8.row.col.f32.tf32.tf32.f32 "
        "{%0,%1,%2,%3},{%4,%5,%6,%7},{%8,%9},{%0,%1,%2,%3};"
        : "+f"(c[0]), "+f"(c[1]), "+f"(c[2]), "+f"(c[3])
        : "r"(a0), "r"(a1), "r"(a2), "r"(a3), "r"(b0), "r"(b1));
}

// Per-group barrier: monotone counter in L2. Writers: __threadfence + relaxed add;
// readers: ld.acquire spin. One barrier per step (d_out[t]/d_out[t+1] double-buffer).
__device__ __forceinline__ void group_barrier(int g, unsigned epoch) {
    __syncthreads();
    if (threadIdx.x == 0) {
        __threadfence();
        atomicAdd(&g_bar[g], 1u);
        const unsigned target = epoch * (unsigned)CPG;
        while (ld_acq(&g_bar[g]) < target) {}
    }
    __syncthreads();
}

__global__ void __launch_bounds__(THREADS, 1)
rnn_kernel(const float* __restrict__ inputs, const float* __restrict__ init,
           const float* __restrict__ noise, const float* __restrict__ wih,
           const float* __restrict__ whh, const float* __restrict__ bias,
           float* __restrict__ out, int T) {
    extern __shared__ float smem[];
    float* Ws = smem + WS_OFF;
    float* As = smem + AS_OFF;
    float* Bs = smem + BIAS_OFF;

    const int g = blockIdx.x / CPG;
    const int cid = blockIdx.x % CPG;
    const int m0 = g * MT;     // batch-row base of this group
    const int n0 = cid * NT;   // output-column base of this CTA
    const int tid = threadIdx.x;
    const int lane = tid & 31;
    const int warp = tid >> 5;
    const int gid = lane >> 2;  // 0..7
    const int qid = lane & 3;   // 0..3
    const int am = (warp >> 2) * 16;  // warp row base in tile (0/16)
    const int an = (warp & 3) * 16;   // warp col base in tile (0/16/32/48)

    // ---- one-time: stage W' = [whh (diag-masked) ; wih ; 0] transposed ->
    //      Ws[n][k], tf32. Extended-K GEMM makes the epilogue pure elementwise.
    for (int idx = tid; idx < NT * KK; idx += THREADS) {
        const int n = idx & (NT - 1);
        const int k = idx >> 6;
        float w;
        if (k < Hh) {
            w = whh[k * Hh + (n0 + n)];
            if (k == n0 + n) w = 0.f;   // forward masks the diagonal
        } else if (k - Hh < Ii) {
            w = wih[(k - Hh) * Hh + (n0 + n)];
        } else {
            w = 0.f;
        }
        Ws[n * STR + k] = __uint_as_float(tf32_rna(w));
    }
    if (tid < NT) Bs[tid] = bias[n0 + tid];

    // ---- init: previous state lives in the accumulator-fragment registers.
    float prev[2][4];
#pragma unroll
    for (int j = 0; j < 2; j++) {
        const int col = n0 + an + j * 8 + 2 * qid;
        const size_t r0 = (size_t)(m0 + am + gid) * Hh + col;
        float2 v0 = *reinterpret_cast<const float2*>(&init[r0]);
        float2 v1 = *reinterpret_cast<const float2*>(&init[r0 + 8 * Hh]);
        prev[j][0] = v0.x; prev[j][1] = v0.y; prev[j][2] = v1.x; prev[j][3] = v1.y;
        *reinterpret_cast<float2*>(&out[r0]) = v0;              // out[0] = initial_state
        *reinterpret_cast<float2*>(&out[r0 + 8 * Hh]) = v1;
    }

    group_barrier(g, 1u);

    for (int t = 0; t < T; t++) {
        const float* st = out + (size_t)t * Bb * Hh;        // state_t (written last step)
        const float* xin = inputs + (size_t)t * Bb * Ii;
        const float* nz = noise + (size_t)t * Bb * Hh;
        float* o1 = out + (size_t)(t + 1) * Bb * Hh;

        // Prefetch this thread's noise tile early (hide DRAM latency behind MMA).
        float2 nzr[2][2];
#pragma unroll
        for (int j = 0; j < 2; j++) {
            const int col = n0 + an + j * 8 + 2 * qid;
            const size_t b0i = (size_t)(m0 + am + gid) * Hh + col;
            nzr[j][0] = *reinterpret_cast<const float2*>(&nz[b0i]);
            nzr[j][1] = *reinterpret_cast<const float2*>(&nz[b0i + 8 * Hh]);
        }

        // Stage A rows: relu(state_t) in tf32 (k < 512). L2-hot reads.
#pragma unroll 4
        for (int idx = tid; idx < MT * (Hh / 4); idx += THREADS) {
            const int r = idx >> 7;
            const int c4 = (idx & 127) << 2;
            float4 v = *reinterpret_cast<const float4*>(&st[(size_t)(m0 + r) * Hh + c4]);
            v.x = tf32f(fmaxf(v.x, 0.f));
            v.y = tf32f(fmaxf(v.y, 0.f));
            v.z = tf32f(fmaxf(v.z, 0.f));
            v.w = tf32f(fmaxf(v.w, 0.f));
            *reinterpret_cast<float4*>(&As[r * STR + c4]) = v;
        }
        // Stage A input-projection columns (k = 512..527): raw inputs, no relu.
        for (int idx = tid; idx < MT * 16; idx += THREADS) {
            const int r = idx >> 4;
            const int kk = idx & 15;
            const float v = (kk < Ii) ? xin[(size_t)(m0 + r) * Ii + kk] : 0.f;
            As[r * STR + Hh + kk] = __uint_as_float(tf32_rna(v));
        }
        __syncthreads();

        // ---- 32x64x528 tf32 GEMM: 66 k-chunks, 2 HMMA per chunk per warp.
        float acc0[4] = {0.f, 0.f, 0.f, 0.f};
        float acc1[4] = {0.f, 0.f, 0.f, 0.f};
        const float* Ap = &As[(am + gid) * STR + qid];
        const float* Bp0 = &Ws[(an + gid) * STR + qid];
        const float* Bp1 = Bp0 + 8 * STR;
#pragma unroll 6
        for (int kb = 0; kb < KK; kb += 8) {
            const uint32_t a0 = __float_as_uint(Ap[kb]);
            const uint32_t a1 = __float_as_uint(Ap[kb + 8 * STR]);
            const uint32_t a2 = __float_as_uint(Ap[kb + 4]);
            const uint32_t a3 = __float_as_uint(Ap[kb + 8 * STR + 4]);
            const uint32_t b00 = __float_as_uint(Bp0[kb]);
            const uint32_t b01 = __float_as_uint(Bp0[kb + 4]);
            const uint32_t b10 = __float_as_uint(Bp1[kb]);
            const uint32_t b11 = __float_as_uint(Bp1[kb + 4]);
            mma_tf32(acc0, a0, a1, a2, a3, b00, b01);
            mma_tf32(acc1, a0, a1, a2, a3, b10, b11);
        }

        // ---- epilogue: state_{t+1} = 0.8*state_t + 0.2*(gemm + bias + sigma*noise)
#pragma unroll
        for (int j = 0; j < 2; j++) {
            float* acc = j ? acc1 : acc0;
            const int lcol = an + j * 8 + 2 * qid;
            const float bia0 = Bs[lcol];
            const float bia1 = Bs[lcol + 1];
            const size_t b0i = (size_t)(m0 + am + gid) * Hh + (n0 + lcol);
            float2 o_lo, o_hi;
            o_lo.x = LEAK * prev[j][0] + ALPHA_ * (acc[0] + bia0 + SIGMA_ * nzr[j][0].x);
            o_lo.y = LEAK * prev[j][1] + ALPHA_ * (acc[1] + bia1 + SIGMA_ * nzr[j][0].y);
            o_hi.x = LEAK * prev[j][2] + ALPHA_ * (acc[2] + bia0 + SIGMA_ * nzr[j][1].x);
            o_hi.y = LEAK * prev[j][3] + ALPHA_ * (acc[3] + bia1 + SIGMA_ * nzr[j][1].y);
            prev[j][0] = o_lo.x; prev[j][1] = o_lo.y;
            prev[j][2] = o_hi.x; prev[j][3] = o_hi.y;
            *reinterpret_cast<float2*>(&o1[b0i]) = o_lo;
            *reinterpret_cast<float2*>(&o1[b0i + 8 * Hh]) = o_hi;
        }

        if (t + 1 < T) group_barrier(g, (unsigned)(t + 2));
    }
}

extern "C" void kernel_launch(void* const* d_in, const int* in_sizes, int n_in,
                              void* d_out, int out_size) {
    (void)n_in; (void)out_size;
    const float* inputs = (const float*)d_in[0];
    const float* init   = (const float*)d_in[1];
    const float* noise  = (const float*)d_in[2];
    const float* wih    = (const float*)d_in[3];
    const float* whh    = (const float*)d_in[4];
    const float* bias   = (const float*)d_in[5];
    float* out = (float*)d_out;

    const int T = in_sizes[2] / (Bb * Hh);   // noise is [T, B, H]

    // Reset per-group barrier counters every launch (graph-capturable memset).
    void* barp = nullptr;
    cudaGetSymbolAddress(&barp, g_bar);
    cudaMemsetAsync(barp, 0, GROUPS * sizeof(unsigned));

    cudaFuncSetAttribute(rnn_kernel, cudaFuncAttributeMaxDynamicSharedMemorySize,
                         SMEM_BYTES);
    rnn_kernel<<<GROUPS * CPG, THREADS, SMEM_BYTES>>>(inputs, init, noise, wih,
                                                      whh, bias, out, T);
}